// round 4
// baseline (speedup 1.0000x reference)
#include <cuda_runtime.h>
#include <cuda_bf16.h>
#include <cstdint>

#define V_SIZE 50257
#define NP     50304          // 393 * 128 (padded vocab)
#define KDIM   768
#define MROWS  2048
#define HD     769
#define LOG_V  10.8249046870f
#define LOG2E  1.44269504089f

// tcgen05 path only in arch-specific / family-specific passes (sm_103a / sm_103f).
#if defined(__CUDA_ARCH__) && (defined(__CUDA_ARCH_FEAT_SM103_ALL) || \
    defined(__CUDA_ARCH_FEAT_SM100_ALL) || defined(__CUDA_ARCH_SPECIFIC__) || \
    defined(__CUDA_ARCH_FAMILY_SPECIFIC__))
#define USE_TCGEN05 1
#else
#define USE_TCGEN05 0
#endif

#define STAGES      3
#define NKT5        12        // KDIM / 64 (tcgen05 path, BK=64)
#define STAGE_BYTES 32768     // A 16KB + B 16KB
#define DYN_SMEM    (STAGES * STAGE_BYTES + 1024)

// -------- scratch (device globals; no allocation allowed) --------
__device__ __align__(16) __nv_bfloat16 g_Wn[(size_t)NP * KDIM];   // ~77 MB
__device__ __align__(16) __nv_bfloat16 g_Un[(size_t)MROWS * KDIM];
__device__ float g_rs[MROWS];
__device__ float g_S1[MROWS];
__device__ float g_S2[MROWS];
__device__ float g_S3[MROWS];

__device__ __forceinline__ void cpa16(uint32_t saddr, const void* gaddr) {
    asm volatile("cp.async.cg.shared.global [%0], [%1], 16;\n"
                 :: "r"(saddr), "l"(gaddr));
}

// ---------------- prep: normalize W_vocab rows -> bf16 (warp per row) --------
__global__ __launch_bounds__(256) void prep_w_kernel(const float* __restrict__ W) {
    const int warp = threadIdx.x >> 5, lane = threadIdx.x & 31;
    const int v = blockIdx.x * 8 + warp;
    __nv_bfloat16* dst = g_Wn + (size_t)v * KDIM;
    if (v >= V_SIZE) {
        #pragma unroll
        for (int j = 0; j < 24; ++j) dst[lane + j * 32] = __float2bfloat16(0.f);
        return;
    }
    const float* row = W + (size_t)v * HD + 1;
    float f[24]; float ss = 0.f;
    #pragma unroll
    for (int j = 0; j < 24; ++j) { f[j] = row[lane + j * 32]; ss = fmaf(f[j], f[j], ss); }
    #pragma unroll
    for (int o = 16; o > 0; o >>= 1) ss += __shfl_xor_sync(0xffffffffu, ss, o);
    const float inv = rsqrtf(fmaxf(ss, 1e-24f));
    #pragma unroll
    for (int j = 0; j < 24; ++j) dst[lane + j * 32] = __float2bfloat16(f[j] * inv);
}

// ---------------- prep: normalize h_student rows, r_s, zero accumulators -----
__global__ __launch_bounds__(256) void prep_s_kernel(const float* __restrict__ H) {
    const int warp = threadIdx.x >> 5, lane = threadIdx.x & 31;
    const int m = blockIdx.x * 8 + warp;
    const float* row = H + (size_t)m * HD + 1;
    float f[24]; float ss = 0.f;
    #pragma unroll
    for (int j = 0; j < 24; ++j) { f[j] = row[lane + j * 32]; ss = fmaf(f[j], f[j], ss); }
    #pragma unroll
    for (int o = 16; o > 0; o >>= 1) ss += __shfl_xor_sync(0xffffffffu, ss, o);
    if (lane == 0) {
        float x0 = fmaxf(H[(size_t)m * HD], 1.f + 1e-7f);
        g_rs[m] = acoshf(x0);
        g_S1[m] = 0.f; g_S2[m] = 0.f; g_S3[m] = 0.f;
    }
    const float inv = rsqrtf(fmaxf(ss, 1e-24f));
    __nv_bfloat16* dst = g_Un + (size_t)m * KDIM;
    #pragma unroll
    for (int j = 0; j < 24; ++j) dst[lane + j * 32] = __float2bfloat16(f[j] * inv);
}

// ---------------- fused GEMM + softmax-KL reductions ----------------
extern __shared__ char dynsm[];

#if USE_TCGEN05
__device__ __forceinline__ uint32_t elect_one() {
    uint32_t p;
    asm volatile("{\n\t.reg .pred p;\n\telect.sync _|p, 0xFFFFFFFF;\n\t"
                 "selp.b32 %0, 1, 0, p;\n\t}" : "=r"(p));
    return p;
}
__device__ __forceinline__ void mbar_wait(uint32_t addr, uint32_t parity) {
    asm volatile(
        "{\n\t.reg .pred P1;\n\t"
        "WAIT_LOOP_%=:\n\t"
        "mbarrier.try_wait.parity.acquire.cta.shared::cta.b64 P1, [%0], %1, 0x989680;\n\t"
        "@P1 bra.uni WAIT_DONE_%=;\n\t"
        "bra.uni WAIT_LOOP_%=;\n\t"
        "WAIT_DONE_%=:\n\t}"
        :: "r"(addr), "r"(parity) : "memory");
}
#endif

__global__ __launch_bounds__(256, 2) void gemm_fused_kernel(const float* __restrict__ P) {
    const int tid  = threadIdx.x;
    const int lane = tid & 31;
    const int warp = tid >> 5;
    const int mt   = blockIdx.x;   // fast -> 16 CTAs share one W tile via L2
    const int nt   = blockIdx.y;

#if USE_TCGEN05
    // ======================= tcgen05 path (sm_103a) =======================
    __shared__ __align__(8) unsigned long long mbar[STAGES];
    __shared__ uint32_t tmem_ptr_s[1];

    const uint32_t smraw  = (uint32_t)__cvta_generic_to_shared(dynsm);
    const uint32_t smbase = (smraw + 1023u) & ~1023u;      // SW128 needs 1KB align
    const uint32_t mbar0  = (uint32_t)__cvta_generic_to_shared(mbar);
    const uint32_t tptr   = (uint32_t)__cvta_generic_to_shared(tmem_ptr_s);

    if (warp == 0) {
        asm volatile("tcgen05.alloc.cta_group::1.sync.aligned.shared::cta.b32 [%0], %1;"
                     :: "r"(tptr), "r"(128u) : "memory");
        asm volatile("tcgen05.relinquish_alloc_permit.cta_group::1.sync.aligned;");
    }
    if (tid == 0) {
        #pragma unroll
        for (int s = 0; s < STAGES; ++s)
            asm volatile("mbarrier.init.shared.b64 [%0], 1;"
                         :: "r"(mbar0 + s * 8) : "memory");
    }
    __syncthreads();
    uint32_t tmem;
    asm volatile("ld.shared.b32 %0, [%1];" : "=r"(tmem) : "r"(tptr));

    const char* GA = (const char*)(g_Un + (size_t)mt * 128 * KDIM);
    const char* GB = (const char*)(g_Wn + (size_t)nt * 128 * KDIM);

    auto load_stage = [&](int kt, int s) {
        const uint32_t abase = smbase + s * STAGE_BYTES;
        const uint32_t bbase = abase + 16384u;
        #pragma unroll
        for (int i = 0; i < 4; ++i) {
            const int c   = tid + i * 256;
            const int row = c >> 3;
            const int c16 = (c & 7) * 16;
            const uint32_t off = (uint32_t)(row * 128 + c16);
            const uint32_t sw  = off ^ ((off >> 3) & 0x70u);
            const size_t gofs  = (size_t)row * (KDIM * 2) + (size_t)kt * 128 + c16;
            cpa16(abase + sw, GA + gofs);
            cpa16(bbase + sw, GB + gofs);
        }
        asm volatile("cp.async.commit_group;\n" ::: "memory");
    };

    #pragma unroll
    for (int s = 0; s < STAGES; ++s) load_stage(s, s);

    // idesc: f32 accum, bf16 x bf16, N=128, M=128
    const uint32_t IDESC = (1u << 4) | (1u << 7) | (1u << 10)
                         | ((128u / 8u) << 17) | ((128u / 16u) << 24);
    const uint64_t DESC_BASE = (2ull << 61) | (1ull << 46) | (64ull << 32) | (1ull << 16);

    uint32_t ph0 = 0, ph1 = 0, ph2 = 0;

    for (int kt = 0; kt < NKT5; ++kt) {
        asm volatile("cp.async.wait_group 1;\n" ::: "memory");
        asm volatile("fence.proxy.async.shared::cta;" ::: "memory");
        __syncthreads();

        const int s = kt % STAGES;
        if (warp == 0) {
            if (elect_one()) {
                const uint32_t abase = smbase + s * STAGE_BYTES;
                const uint32_t bbase = abase + 16384u;
                const uint64_t ad = DESC_BASE | ((abase >> 4) & 0x3FFFu);
                const uint64_t bd = DESC_BASE | ((bbase >> 4) & 0x3FFFu);
                #pragma unroll
                for (int kk = 0; kk < 4; ++kk) {
                    const uint32_t en = (kt > 0 || kk > 0) ? 1u : 0u;
                    asm volatile(
                        "{\n\t.reg .pred p;\n\tsetp.ne.u32 p, %4, 0;\n\t"
                        "tcgen05.mma.cta_group::1.kind::f16 [%0], %1, %2, %3, "
                        "{%5,%5,%5,%5}, p;\n\t}"
                        :: "r"(tmem), "l"(ad + kk * 2), "l"(bd + kk * 2),
                           "r"(IDESC), "r"(en), "r"(0u)
                        : "memory");
                }
                asm volatile(
                    "tcgen05.commit.cta_group::1.mbarrier::arrive::one.shared::cluster.b64 [%0];"
                    :: "r"(mbar0 + s * 8) : "memory");
            }
        }

        if (kt >= 1 && kt <= NKT5 - 3) {   // refill slot used last iteration
            const int sp = (kt - 1) % STAGES;
            uint32_t ph = (sp == 0) ? ph0 : (sp == 1) ? ph1 : ph2;
            mbar_wait(mbar0 + sp * 8, ph);
            if (sp == 0) ph0 ^= 1; else if (sp == 1) ph1 ^= 1; else ph2 ^= 1;
            load_stage(kt + 2, sp);
        } else {
            asm volatile("cp.async.commit_group;\n" ::: "memory");  // keep 1 group/iter
        }
    }

    // final commit = slot 2 (kt=11); covers all prior MMAs
    mbar_wait(mbar0 + 2 * 8, ph2);
    asm volatile("tcgen05.fence::after_thread_sync;" ::: "memory");

    // ---- epilogue: warp w -> rows (w&3)*32+lane, cols (w>>2)*64 .. +63 ----
    {
        const int sub  = warp & 3;
        const int half = warp >> 2;
        const int r    = mt * 128 + sub * 32 + lane;
        float s1 = 0.f, s2 = 0.f, s3 = 0.f;

        #pragma unroll
        for (int ch = 0; ch < 2; ++ch) {
            uint32_t d[32];
            const uint32_t taddr = tmem + (uint32_t)(half * 64 + ch * 32);
            asm volatile(
                "tcgen05.ld.sync.aligned.32x32b.x32.b32 "
                "{%0,%1,%2,%3,%4,%5,%6,%7,%8,%9,%10,%11,%12,%13,%14,%15,"
                "%16,%17,%18,%19,%20,%21,%22,%23,%24,%25,%26,%27,%28,%29,%30,%31}, [%32];"
                : "=r"(d[0]),  "=r"(d[1]),  "=r"(d[2]),  "=r"(d[3]),
                  "=r"(d[4]),  "=r"(d[5]),  "=r"(d[6]),  "=r"(d[7]),
                  "=r"(d[8]),  "=r"(d[9]),  "=r"(d[10]), "=r"(d[11]),
                  "=r"(d[12]), "=r"(d[13]), "=r"(d[14]), "=r"(d[15]),
                  "=r"(d[16]), "=r"(d[17]), "=r"(d[18]), "=r"(d[19]),
                  "=r"(d[20]), "=r"(d[21]), "=r"(d[22]), "=r"(d[23]),
                  "=r"(d[24]), "=r"(d[25]), "=r"(d[26]), "=r"(d[27]),
                  "=r"(d[28]), "=r"(d[29]), "=r"(d[30]), "=r"(d[31])
                : "r"(taddr));
            asm volatile("tcgen05.wait::ld.sync.aligned;" ::: "memory");

            const int v0 = nt * 128 + half * 64 + ch * 32;
            const float* Pr = P + (size_t)r * V_SIZE + v0;
            #pragma unroll
            for (int j = 0; j < 32; ++j) {
                if (v0 + j < V_SIZE) {
                    const float lg = __uint_as_float(d[j]);
                    const float p  = __ldg(Pr + j);
                    s1 += exp2f(fmaf(lg, LOG2E, -LOG2E));
                    s2 = fmaf(p, lg, s2);
                    s3 = fmaf(p, __logf(fmaxf(p, 1e-12f)), s3);
                }
            }
        }
        atomicAdd(&g_S1[r], s1);
        atomicAdd(&g_S2[r], s2);
        atomicAdd(&g_S3[r], s3);
    }

    asm volatile("tcgen05.fence::before_thread_sync;" ::: "memory");
    __syncthreads();
    if (warp == 0) {
        asm volatile("tcgen05.dealloc.cta_group::1.sync.aligned.b32 %0, %1;"
                     :: "r"(tmem), "r"(128u));
    }

#else
    // ================= legacy mma.sync fallback (plain sm_103) =================
    const int wm = warp & 3;   // 0..3 along M
    const int wn = warp >> 2;  // 0..1 along N

    __nv_bfloat16* smp = (__nv_bfloat16*)dynsm;  // 4 buffers of 128x40 bf16 = 40KB

    float acc[2][8][4];
    #pragma unroll
    for (int a = 0; a < 2; ++a)
        #pragma unroll
        for (int b = 0; b < 8; ++b)
            #pragma unroll
            for (int c = 0; c < 4; ++c) acc[a][b][c] = 0.f;

    const __nv_bfloat16* GA = g_Un + (size_t)mt * 128 * KDIM;
    const __nv_bfloat16* GB = g_Wn + (size_t)nt * 128 * KDIM;
    const uint32_t smBase = (uint32_t)__cvta_generic_to_shared(smp);

    const int ldrow = tid >> 2;
    const int ldcol = (tid & 3) * 8;

    auto load_stage = [&](int kt, int buf) {
        #pragma unroll
        for (int it = 0; it < 2; ++it) {
            const int r = ldrow + it * 64;
            cpa16(smBase + (uint32_t)((buf * 5120) + r * 40 + ldcol) * 2u,
                  GA + (size_t)r * KDIM + kt * 32 + ldcol);
            cpa16(smBase + (uint32_t)(((2 + buf) * 5120) + r * 40 + ldcol) * 2u,
                  GB + (size_t)r * KDIM + kt * 32 + ldcol);
        }
        asm volatile("cp.async.commit_group;\n" ::: "memory");
    };

    load_stage(0, 0);
    load_stage(1, 1);

    for (int kt = 0; kt < KDIM / 32; ++kt) {
        asm volatile("cp.async.wait_group 1;\n" ::: "memory");
        __syncthreads();

        const int buf = kt & 1;
        const uint32_t aBase = smBase + (uint32_t)(buf * 5120) * 2u;
        const uint32_t bBase = smBase + (uint32_t)((2 + buf) * 5120) * 2u;

        #pragma unroll
        for (int kk = 0; kk < 2; ++kk) {
            const int kb = kk * 16;
            uint32_t a[2][4];
            #pragma unroll
            for (int mi = 0; mi < 2; ++mi) {
                int row = wm * 32 + mi * 16 + (lane & 15);
                int col = kb + ((lane >> 4) << 3);
                uint32_t addr = aBase + (uint32_t)(row * 40 + col) * 2u;
                asm volatile("ldmatrix.sync.aligned.m8n8.x4.shared.b16 {%0,%1,%2,%3}, [%4];"
                    : "=r"(a[mi][0]), "=r"(a[mi][1]), "=r"(a[mi][2]), "=r"(a[mi][3])
                    : "r"(addr));
            }
            #pragma unroll
            for (int np = 0; np < 4; ++np) {
                int row = wn * 64 + np * 16 + ((lane >> 4) & 1) * 8 + (lane & 7);
                int col = kb + ((lane >> 3) & 1) * 8;
                uint32_t addr = bBase + (uint32_t)(row * 40 + col) * 2u;
                uint32_t b0, b1, b2, b3;
                asm volatile("ldmatrix.sync.aligned.m8n8.x4.shared.b16 {%0,%1,%2,%3}, [%4];"
                    : "=r"(b0), "=r"(b1), "=r"(b2), "=r"(b3) : "r"(addr));
                #pragma unroll
                for (int mi = 0; mi < 2; ++mi) {
                    asm volatile(
                        "mma.sync.aligned.m16n8k16.row.col.f32.bf16.bf16.f32 "
                        "{%0,%1,%2,%3}, {%4,%5,%6,%7}, {%8,%9}, {%0,%1,%2,%3};"
                        : "+f"(acc[mi][2 * np][0]), "+f"(acc[mi][2 * np][1]),
                          "+f"(acc[mi][2 * np][2]), "+f"(acc[mi][2 * np][3])
                        : "r"(a[mi][0]), "r"(a[mi][1]), "r"(a[mi][2]), "r"(a[mi][3]),
                          "r"(b0), "r"(b1));
                    asm volatile(
                        "mma.sync.aligned.m16n8k16.row.col.f32.bf16.bf16.f32 "
                        "{%0,%1,%2,%3}, {%4,%5,%6,%7}, {%8,%9}, {%0,%1,%2,%3};"
                        : "+f"(acc[mi][2 * np + 1][0]), "+f"(acc[mi][2 * np + 1][1]),
                          "+f"(acc[mi][2 * np + 1][2]), "+f"(acc[mi][2 * np + 1][3])
                        : "r"(a[mi][0]), "r"(a[mi][1]), "r"(a[mi][2]), "r"(a[mi][3]),
                          "r"(b2), "r"(b3));
                }
            }
        }

        __syncthreads();
        if (kt + 2 < KDIM / 32) load_stage(kt + 2, buf);
        else asm volatile("cp.async.commit_group;\n" ::: "memory");
    }

    const int rowBase = mt * 128 + wm * 32 + (lane >> 2);
    const int colBase = nt * 128 + wn * 64 + ((lane & 3) << 1);

    #pragma unroll
    for (int mi = 0; mi < 2; ++mi) {
        #pragma unroll
        for (int h = 0; h < 2; ++h) {
            const int r = rowBase + mi * 16 + h * 8;
            const float* Prow = P + (size_t)r * V_SIZE;
            float s1 = 0.f, s2 = 0.f, s3 = 0.f;
            #pragma unroll
            for (int ni = 0; ni < 8; ++ni) {
                #pragma unroll
                for (int e = 0; e < 2; ++e) {
                    int v = colBase + ni * 8 + e;
                    if (v < V_SIZE) {
                        float lg = acc[mi][ni][h * 2 + e];
                        float p  = __ldg(Prow + v);
                        s1 += exp2f(fmaf(lg, LOG2E, -LOG2E));
                        s2 = fmaf(p, lg, s2);
                        s3 = fmaf(p, __logf(fmaxf(p, 1e-12f)), s3);
                    }
                }
            }
            s1 += __shfl_xor_sync(0xffffffffu, s1, 1);
            s1 += __shfl_xor_sync(0xffffffffu, s1, 2);
            s2 += __shfl_xor_sync(0xffffffffu, s2, 1);
            s2 += __shfl_xor_sync(0xffffffffu, s2, 2);
            s3 += __shfl_xor_sync(0xffffffffu, s3, 1);
            s3 += __shfl_xor_sync(0xffffffffu, s3, 2);
            if ((lane & 3) == 0) {
                atomicAdd(&g_S1[r], s1);
                atomicAdd(&g_S2[r], s2);
                atomicAdd(&g_S3[r], s3);
            }
        }
    }
#endif
}

// ---------------- finalize: combine per-row stats + radial loss ----------------
__global__ __launch_bounds__(1024) void finalize_kernel(const float* __restrict__ TE,
                                                        float* __restrict__ out) {
    const int t = threadIdx.x;
    float v0 = 0.f, v1 = 0.f, v2 = 0.f, v3 = 0.f, v4 = 0.f;
    for (int r = t; r < MROWS; r += 1024) {
        v0 += g_S3[r] - g_S2[r] + 1.f + __logf(g_S1[r]);   // per-row KL
        float rr = g_rs[r];
        v1 += rr;
        float Hn = fminf(fmaxf(TE[r] * (1.f / LOG_V), 0.f), 1.f);
        float rtg = 3.0f / (1.f + expf(Hn));               // sigmoid(-H) * R_MAX
        float d = rr - rtg;
        v2 = fmaf(d, d, v2);
        v3 += rtg;
        v4 += Hn;
    }
    #pragma unroll
    for (int o = 16; o > 0; o >>= 1) {
        v0 += __shfl_xor_sync(0xffffffffu, v0, o);
        v1 += __shfl_xor_sync(0xffffffffu, v1, o);
        v2 += __shfl_xor_sync(0xffffffffu, v2, o);
        v3 += __shfl_xor_sync(0xffffffffu, v3, o);
        v4 += __shfl_xor_sync(0xffffffffu, v4, o);
    }
    __shared__ float sb[32][5];
    if ((t & 31) == 0) {
        int w = t >> 5;
        sb[w][0] = v0; sb[w][1] = v1; sb[w][2] = v2; sb[w][3] = v3; sb[w][4] = v4;
    }
    __syncthreads();
    if (t < 32) {
        float u0 = sb[t][0], u1 = sb[t][1], u2 = sb[t][2], u3 = sb[t][3], u4 = sb[t][4];
        #pragma unroll
        for (int o = 16; o > 0; o >>= 1) {
            u0 += __shfl_xor_sync(0xffffffffu, u0, o);
            u1 += __shfl_xor_sync(0xffffffffu, u1, o);
            u2 += __shfl_xor_sync(0xffffffffu, u2, o);
            u3 += __shfl_xor_sync(0xffffffffu, u3, o);
            u4 += __shfl_xor_sync(0xffffffffu, u4, o);
        }
        if (t == 0) {
            const float inv = 1.f / (float)MROWS;
            float l_ang = u0 * inv;
            float l_rad = u2 * inv;
            out[0] = l_ang + 0.1f * l_rad;
            out[1] = l_ang;
            out[2] = l_rad;
            out[3] = u1 * inv;   // mean r_s
            out[4] = u3 * inv;   // mean r_target
            out[5] = u4 * inv;   // mean H_norm
        }
    }
}

// ---------------- launch ----------------
extern "C" void kernel_launch(void* const* d_in, const int* in_sizes, int n_in,
                              void* d_out, int out_size) {
    const float* h  = (const float*)d_in[0];   // (2,1024,769)
    const float* W  = (const float*)d_in[1];   // (50257,769)
    const float* P  = (const float*)d_in[2];   // (2,1024,50257)
    const float* TE = (const float*)d_in[3];   // (2,1024)
    float* out = (float*)d_out;

    cudaFuncSetAttribute(gemm_fused_kernel,
                         cudaFuncAttributeMaxDynamicSharedMemorySize, DYN_SMEM);

    prep_w_kernel<<<NP / 8, 256>>>(W);
    prep_s_kernel<<<MROWS / 8, 256>>>(h);
    gemm_fused_kernel<<<dim3(MROWS / 128, NP / 128), 256, DYN_SMEM>>>(P);
    finalize_kernel<<<1, 1024>>>(TE, out);
}

// round 5
// speedup vs baseline: 3.1914x; 3.1914x over previous
#include <cuda_runtime.h>
#include <cuda_bf16.h>
#include <cstdint>

#define V_SIZE 50257
#define NP     50304          // 393 * 128 (padded vocab)
#define NTILES 393
#define KDIM   768
#define MROWS  2048
#define HD     769
#define LOG_V  10.8249046870f
#define LOG2E  1.44269504089f

// tcgen05 path only in arch-specific / family-specific passes (sm_103a / sm_103f).
#if defined(__CUDA_ARCH__) && (defined(__CUDA_ARCH_FEAT_SM103_ALL) || \
    defined(__CUDA_ARCH_FEAT_SM100_ALL) || defined(__CUDA_ARCH_SPECIFIC__) || \
    defined(__CUDA_ARCH_FAMILY_SPECIFIC__))
#define USE_TCGEN05 1
#else
#define USE_TCGEN05 0
#endif

#define STAGES      3
#define NKT5        12        // KDIM / 64 (tcgen05 path, BK=64)
#define STAGE_BYTES 32768     // A 16KB + B 16KB
#define DYN_SMEM    (STAGES * STAGE_BYTES + 1024)

// -------- scratch (device globals; no allocation allowed) --------
__device__ __align__(16) __nv_bfloat16 g_Wn[(size_t)NP * KDIM];   // ~77 MB
__device__ __align__(16) __nv_bfloat16 g_Un[(size_t)MROWS * KDIM];
__device__ float g_rs[MROWS];
__device__ float g_S1[MROWS];
__device__ float g_S2[MROWS];
__device__ float g_S3[MROWS];

__device__ __forceinline__ void cpa16(uint32_t saddr, const void* gaddr) {
    asm volatile("cp.async.cg.shared.global [%0], [%1], 16;\n"
                 :: "r"(saddr), "l"(gaddr));
}

// ---------------- prep: normalize W_vocab rows -> bf16 (warp per row) --------
__global__ __launch_bounds__(256) void prep_w_kernel(const float* __restrict__ W) {
    const int warp = threadIdx.x >> 5, lane = threadIdx.x & 31;
    const int v = blockIdx.x * 8 + warp;
    __nv_bfloat16* dst = g_Wn + (size_t)v * KDIM;
    if (v >= V_SIZE) {
        #pragma unroll
        for (int j = 0; j < 24; ++j) dst[lane + j * 32] = __float2bfloat16(0.f);
        return;
    }
    const float* row = W + (size_t)v * HD + 1;
    float f[24]; float ss = 0.f;
    #pragma unroll
    for (int j = 0; j < 24; ++j) { f[j] = row[lane + j * 32]; ss = fmaf(f[j], f[j], ss); }
    #pragma unroll
    for (int o = 16; o > 0; o >>= 1) ss += __shfl_xor_sync(0xffffffffu, ss, o);
    const float inv = rsqrtf(fmaxf(ss, 1e-24f));
    #pragma unroll
    for (int j = 0; j < 24; ++j) dst[lane + j * 32] = __float2bfloat16(f[j] * inv);
}

// ---------------- prep: normalize h_student rows, r_s, zero accumulators -----
__global__ __launch_bounds__(256) void prep_s_kernel(const float* __restrict__ H) {
    const int warp = threadIdx.x >> 5, lane = threadIdx.x & 31;
    const int m = blockIdx.x * 8 + warp;
    const float* row = H + (size_t)m * HD + 1;
    float f[24]; float ss = 0.f;
    #pragma unroll
    for (int j = 0; j < 24; ++j) { f[j] = row[lane + j * 32]; ss = fmaf(f[j], f[j], ss); }
    #pragma unroll
    for (int o = 16; o > 0; o >>= 1) ss += __shfl_xor_sync(0xffffffffu, ss, o);
    if (lane == 0) {
        float x0 = fmaxf(H[(size_t)m * HD], 1.f + 1e-7f);
        g_rs[m] = acoshf(x0);
        g_S1[m] = 0.f; g_S2[m] = 0.f; g_S3[m] = 0.f;
    }
    const float inv = rsqrtf(fmaxf(ss, 1e-24f));
    __nv_bfloat16* dst = g_Un + (size_t)m * KDIM;
    #pragma unroll
    for (int j = 0; j < 24; ++j) dst[lane + j * 32] = __float2bfloat16(f[j] * inv);
}

// ---------------- fused GEMM + softmax-KL reductions ----------------
extern __shared__ char dynsm[];

#if USE_TCGEN05
__device__ __forceinline__ uint32_t elect_one() {
    uint32_t p;
    asm volatile("{\n\t.reg .pred p;\n\telect.sync _|p, 0xFFFFFFFF;\n\t"
                 "selp.b32 %0, 1, 0, p;\n\t}" : "=r"(p));
    return p;
}
__device__ __forceinline__ void mbar_wait(uint32_t addr, uint32_t parity) {
    asm volatile(
        "{\n\t.reg .pred P1;\n\t"
        "WAIT_LOOP_%=:\n\t"
        "mbarrier.try_wait.parity.acquire.cta.shared::cta.b64 P1, [%0], %1, 0x989680;\n\t"
        "@P1 bra.uni WAIT_DONE_%=;\n\t"
        "bra.uni WAIT_LOOP_%=;\n\t"
        "WAIT_DONE_%=:\n\t}"
        :: "r"(addr), "r"(parity) : "memory");
}
#endif

// Cooperative, coalesced load of the CTA's 128x128 P tile into smem.
// Smem layout: float4-granular XOR swizzle: float4 slot (row, c4) stored at
// [row*32 + (c4 ^ (row & 31))]. Conflict-free for row-major scalar STS and
// per-lane (lane==row%32) float4 LDS.
__device__ __forceinline__ void load_p_tile(float* Psm, const float* __restrict__ P,
                                            int mt, int nt, int tid) {
    if (nt < NTILES - 1) {
        #pragma unroll
        for (int j = 0; j < 64; ++j) {
            const int idx = tid + j * 256;
            const int row = idx >> 7, col = idx & 127;
            const float val = __ldg(P + (size_t)(mt * 128 + row) * V_SIZE + nt * 128 + col);
            Psm[(row << 7) + (((col >> 2) ^ (row & 31)) << 2) + (col & 3)] = val;
        }
    } else {
        #pragma unroll
        for (int j = 0; j < 64; ++j) {
            const int idx = tid + j * 256;
            const int row = idx >> 7, col = idx & 127;
            const int v = nt * 128 + col;
            const float val = (v < V_SIZE)
                ? __ldg(P + (size_t)(mt * 128 + row) * V_SIZE + v) : 0.f;
            Psm[(row << 7) + (((col >> 2) ^ (row & 31)) << 2) + (col & 3)] = val;
        }
    }
}

__global__ __launch_bounds__(256, 2) void gemm_fused_kernel(const float* __restrict__ P) {
    const int tid  = threadIdx.x;
    const int lane = tid & 31;
    const int warp = tid >> 5;
    const int mt   = blockIdx.x;   // fast -> 16 CTAs share one W tile via L2
    const int nt   = blockIdx.y;

#if USE_TCGEN05
    // ======================= tcgen05 path (sm_103a) =======================
    __shared__ __align__(8) unsigned long long mbar[STAGES];
    __shared__ uint32_t tmem_ptr_s[1];

    const uint32_t smraw  = (uint32_t)__cvta_generic_to_shared(dynsm);
    const uint32_t smbase = (smraw + 1023u) & ~1023u;      // SW128 needs 1KB align
    const uint32_t mbar0  = (uint32_t)__cvta_generic_to_shared(mbar);
    const uint32_t tptr   = (uint32_t)__cvta_generic_to_shared(tmem_ptr_s);

    if (warp == 0) {
        asm volatile("tcgen05.alloc.cta_group::1.sync.aligned.shared::cta.b32 [%0], %1;"
                     :: "r"(tptr), "r"(128u) : "memory");
        asm volatile("tcgen05.relinquish_alloc_permit.cta_group::1.sync.aligned;");
    }
    if (tid == 0) {
        #pragma unroll
        for (int s = 0; s < STAGES; ++s)
            asm volatile("mbarrier.init.shared.b64 [%0], 1;"
                         :: "r"(mbar0 + s * 8) : "memory");
    }
    __syncthreads();
    uint32_t tmem;
    asm volatile("ld.shared.b32 %0, [%1];" : "=r"(tmem) : "r"(tptr));

    const char* GA = (const char*)(g_Un + (size_t)mt * 128 * KDIM);
    const char* GB = (const char*)(g_Wn + (size_t)nt * 128 * KDIM);

    auto load_stage = [&](int kt, int s) {
        const uint32_t abase = smbase + s * STAGE_BYTES;
        const uint32_t bbase = abase + 16384u;
        #pragma unroll
        for (int i = 0; i < 4; ++i) {
            const int c   = tid + i * 256;
            const int row = c >> 3;
            const int c16 = (c & 7) * 16;
            const uint32_t off = (uint32_t)(row * 128 + c16);
            const uint32_t sw  = off ^ ((off >> 3) & 0x70u);
            const size_t gofs  = (size_t)row * (KDIM * 2) + (size_t)kt * 128 + c16;
            cpa16(abase + sw, GA + gofs);
            cpa16(bbase + sw, GB + gofs);
        }
        asm volatile("cp.async.commit_group;\n" ::: "memory");
    };

    #pragma unroll
    for (int s = 0; s < STAGES; ++s) load_stage(s, s);

    // idesc: f32 accum, bf16 x bf16, N=128, M=128
    const uint32_t IDESC = (1u << 4) | (1u << 7) | (1u << 10)
                         | ((128u / 8u) << 17) | ((128u / 16u) << 24);
    const uint64_t DESC_BASE = (2ull << 61) | (1ull << 46) | (64ull << 32) | (1ull << 16);

    uint32_t ph0 = 0, ph1 = 0, ph2 = 0;

    for (int kt = 0; kt < NKT5; ++kt) {
        asm volatile("cp.async.wait_group 1;\n" ::: "memory");
        asm volatile("fence.proxy.async.shared::cta;" ::: "memory");
        __syncthreads();

        const int s = kt % STAGES;
        if (warp == 0) {
            if (elect_one()) {
                const uint32_t abase = smbase + s * STAGE_BYTES;
                const uint32_t bbase = abase + 16384u;
                const uint64_t ad = DESC_BASE | ((abase >> 4) & 0x3FFFu);
                const uint64_t bd = DESC_BASE | ((bbase >> 4) & 0x3FFFu);
                #pragma unroll
                for (int kk = 0; kk < 4; ++kk) {
                    const uint32_t en = (kt > 0 || kk > 0) ? 1u : 0u;
                    asm volatile(
                        "{\n\t.reg .pred p;\n\tsetp.ne.u32 p, %4, 0;\n\t"
                        "tcgen05.mma.cta_group::1.kind::f16 [%0], %1, %2, %3, "
                        "{%5,%5,%5,%5}, p;\n\t}"
                        :: "r"(tmem), "l"(ad + kk * 2), "l"(bd + kk * 2),
                           "r"(IDESC), "r"(en), "r"(0u)
                        : "memory");
                }
                asm volatile(
                    "tcgen05.commit.cta_group::1.mbarrier::arrive::one.shared::cluster.b64 [%0];"
                    :: "r"(mbar0 + s * 8) : "memory");
            }
        }

        if (kt >= 1 && kt <= NKT5 - 3) {   // refill slot used last iteration
            const int sp = (kt - 1) % STAGES;
            uint32_t ph = (sp == 0) ? ph0 : (sp == 1) ? ph1 : ph2;
            mbar_wait(mbar0 + sp * 8, ph);
            if (sp == 0) ph0 ^= 1; else if (sp == 1) ph1 ^= 1; else ph2 ^= 1;
            load_stage(kt + 2, sp);
        } else {
            asm volatile("cp.async.commit_group;\n" ::: "memory");  // keep 1 group/iter
        }
    }

    // final commit = slot 2 (kt=11); covers all prior MMAs
    mbar_wait(mbar0 + 2 * 8, ph2);
    asm volatile("tcgen05.fence::after_thread_sync;" ::: "memory");

    // ---- epilogue: coalesced P -> smem, then per-lane conflict-free LDS ----
    {
        float* Psm = (float*)(dynsm + (smbase - smraw));   // reuse stage smem (64KB)
        load_p_tile(Psm, P, mt, nt, tid);
        __syncthreads();

        const int sub  = warp & 3;
        const int half = warp >> 2;
        const int lrow = sub * 32 + lane;    // local row == TMEM lane
        const int r    = mt * 128 + lrow;
        const float4* Psm4 = (const float4*)Psm;
        float s1 = 0.f, s2 = 0.f, s3 = 0.f;

        #pragma unroll
        for (int ch = 0; ch < 2; ++ch) {
            uint32_t d[32];
            const uint32_t taddr = tmem + (uint32_t)(half * 64 + ch * 32);
            asm volatile(
                "tcgen05.ld.sync.aligned.32x32b.x32.b32 "
                "{%0,%1,%2,%3,%4,%5,%6,%7,%8,%9,%10,%11,%12,%13,%14,%15,"
                "%16,%17,%18,%19,%20,%21,%22,%23,%24,%25,%26,%27,%28,%29,%30,%31}, [%32];"
                : "=r"(d[0]),  "=r"(d[1]),  "=r"(d[2]),  "=r"(d[3]),
                  "=r"(d[4]),  "=r"(d[5]),  "=r"(d[6]),  "=r"(d[7]),
                  "=r"(d[8]),  "=r"(d[9]),  "=r"(d[10]), "=r"(d[11]),
                  "=r"(d[12]), "=r"(d[13]), "=r"(d[14]), "=r"(d[15]),
                  "=r"(d[16]), "=r"(d[17]), "=r"(d[18]), "=r"(d[19]),
                  "=r"(d[20]), "=r"(d[21]), "=r"(d[22]), "=r"(d[23]),
                  "=r"(d[24]), "=r"(d[25]), "=r"(d[26]), "=r"(d[27]),
                  "=r"(d[28]), "=r"(d[29]), "=r"(d[30]), "=r"(d[31])
                : "r"(taddr));
            asm volatile("tcgen05.wait::ld.sync.aligned;" ::: "memory");

            const int colb = half * 64 + ch * 32;
            const int c4b  = colb >> 2;
            #pragma unroll
            for (int jj = 0; jj < 8; ++jj) {
                const float4 p4 = Psm4[(lrow << 5) + ((c4b + jj) ^ (lrow & 31))];
                const float pv[4] = {p4.x, p4.y, p4.z, p4.w};
                #pragma unroll
                for (int e = 0; e < 4; ++e) {
                    const int v = nt * 128 + colb + jj * 4 + e;
                    if (v < V_SIZE) {
                        const float lg = __uint_as_float(d[jj * 4 + e]);
                        const float p  = pv[e];
                        s1 += exp2f(fmaf(lg, LOG2E, -LOG2E));
                        s2 = fmaf(p, lg, s2);
                        s3 = fmaf(p, __logf(fmaxf(p, 1e-12f)), s3);
                    }
                }
            }
        }
        atomicAdd(&g_S1[r], s1);
        atomicAdd(&g_S2[r], s2);
        atomicAdd(&g_S3[r], s3);
    }

    asm volatile("tcgen05.fence::before_thread_sync;" ::: "memory");
    __syncthreads();
    if (warp == 0) {
        asm volatile("tcgen05.dealloc.cta_group::1.sync.aligned.b32 %0, %1;"
                     :: "r"(tmem), "r"(128u));
    }

#else
    // ================= legacy mma.sync fallback (plain sm_103) =================
    const int wm = warp & 3;   // 0..3 along M
    const int wn = warp >> 2;  // 0..1 along N

    __nv_bfloat16* smp = (__nv_bfloat16*)dynsm;  // 4 buffers of 128x40 bf16 = 40KB

    float acc[2][8][4];
    #pragma unroll
    for (int a = 0; a < 2; ++a)
        #pragma unroll
        for (int b = 0; b < 8; ++b)
            #pragma unroll
            for (int c = 0; c < 4; ++c) acc[a][b][c] = 0.f;

    const __nv_bfloat16* GA = g_Un + (size_t)mt * 128 * KDIM;
    const __nv_bfloat16* GB = g_Wn + (size_t)nt * 128 * KDIM;
    const uint32_t smBase = (uint32_t)__cvta_generic_to_shared(smp);

    const int ldrow = tid >> 2;
    const int ldcol = (tid & 3) * 8;

    auto load_stage = [&](int kt, int buf) {
        #pragma unroll
        for (int it = 0; it < 2; ++it) {
            const int r = ldrow + it * 64;
            cpa16(smBase + (uint32_t)((buf * 5120) + r * 40 + ldcol) * 2u,
                  GA + (size_t)r * KDIM + kt * 32 + ldcol);
            cpa16(smBase + (uint32_t)(((2 + buf) * 5120) + r * 40 + ldcol) * 2u,
                  GB + (size_t)r * KDIM + kt * 32 + ldcol);
        }
        asm volatile("cp.async.commit_group;\n" ::: "memory");
    };

    load_stage(0, 0);
    load_stage(1, 1);

    for (int kt = 0; kt < KDIM / 32; ++kt) {
        asm volatile("cp.async.wait_group 1;\n" ::: "memory");
        __syncthreads();

        const int buf = kt & 1;
        const uint32_t aBase = smBase + (uint32_t)(buf * 5120) * 2u;
        const uint32_t bBase = smBase + (uint32_t)((2 + buf) * 5120) * 2u;

        #pragma unroll
        for (int kk = 0; kk < 2; ++kk) {
            const int kb = kk * 16;
            uint32_t a[2][4];
            #pragma unroll
            for (int mi = 0; mi < 2; ++mi) {
                int row = wm * 32 + mi * 16 + (lane & 15);
                int col = kb + ((lane >> 4) << 3);
                uint32_t addr = aBase + (uint32_t)(row * 40 + col) * 2u;
                asm volatile("ldmatrix.sync.aligned.m8n8.x4.shared.b16 {%0,%1,%2,%3}, [%4];"
                    : "=r"(a[mi][0]), "=r"(a[mi][1]), "=r"(a[mi][2]), "=r"(a[mi][3])
                    : "r"(addr));
            }
            #pragma unroll
            for (int np = 0; np < 4; ++np) {
                int row = wn * 64 + np * 16 + ((lane >> 4) & 1) * 8 + (lane & 7);
                int col = kb + ((lane >> 3) & 1) * 8;
                uint32_t addr = bBase + (uint32_t)(row * 40 + col) * 2u;
                uint32_t b0, b1, b2, b3;
                asm volatile("ldmatrix.sync.aligned.m8n8.x4.shared.b16 {%0,%1,%2,%3}, [%4];"
                    : "=r"(b0), "=r"(b1), "=r"(b2), "=r"(b3) : "r"(addr));
                #pragma unroll
                for (int mi = 0; mi < 2; ++mi) {
                    asm volatile(
                        "mma.sync.aligned.m16n8k16.row.col.f32.bf16.bf16.f32 "
                        "{%0,%1,%2,%3}, {%4,%5,%6,%7}, {%8,%9}, {%0,%1,%2,%3};"
                        : "+f"(acc[mi][2 * np][0]), "+f"(acc[mi][2 * np][1]),
                          "+f"(acc[mi][2 * np][2]), "+f"(acc[mi][2 * np][3])
                        : "r"(a[mi][0]), "r"(a[mi][1]), "r"(a[mi][2]), "r"(a[mi][3]),
                          "r"(b0), "r"(b1));
                    asm volatile(
                        "mma.sync.aligned.m16n8k16.row.col.f32.bf16.bf16.f32 "
                        "{%0,%1,%2,%3}, {%4,%5,%6,%7}, {%8,%9}, {%0,%1,%2,%3};"
                        : "+f"(acc[mi][2 * np + 1][0]), "+f"(acc[mi][2 * np + 1][1]),
                          "+f"(acc[mi][2 * np + 1][2]), "+f"(acc[mi][2 * np + 1][3])
                        : "r"(a[mi][0]), "r"(a[mi][1]), "r"(a[mi][2]), "r"(a[mi][3]),
                          "r"(b2), "r"(b3));
                }
            }
        }

        __syncthreads();
        if (kt + 2 < KDIM / 32) load_stage(kt + 2, buf);
        else asm volatile("cp.async.commit_group;\n" ::: "memory");
    }

    // ---- epilogue: coalesced P -> smem, then low-conflict LDS.64 reads ----
    __syncthreads();                         // mainloop smem fully consumed
    asm volatile("cp.async.wait_group 0;\n" ::: "memory");
    float* Psm = (float*)dynsm;              // 64KB P tile over stage smem
    load_p_tile(Psm, P, mt, nt, tid);
    __syncthreads();

    const int rowBase = wm * 32 + (lane >> 2);
    const int colBase = wn * 64 + ((lane & 3) << 1);

    #pragma unroll
    for (int mi = 0; mi < 2; ++mi) {
        #pragma unroll
        for (int h = 0; h < 2; ++h) {
            const int rl = rowBase + mi * 16 + h * 8;
            const int r  = mt * 128 + rl;
            float s1 = 0.f, s2 = 0.f, s3 = 0.f;
            #pragma unroll
            for (int ni = 0; ni < 8; ++ni) {
                const int col0 = colBase + ni * 8;
                const int c4   = col0 >> 2;
                const float2 p2 = *(const float2*)&Psm[(rl << 7) +
                                   ((c4 ^ (rl & 31)) << 2) + (col0 & 3)];
                const float pv[2] = {p2.x, p2.y};
                #pragma unroll
                for (int e = 0; e < 2; ++e) {
                    const int v = nt * 128 + col0 + e;
                    if (v < V_SIZE) {
                        const float lg = acc[mi][2 * (ni >> 1) + (ni & 1)][h * 2 + e];
                        const float p  = pv[e];
                        s1 += exp2f(fmaf(lg, LOG2E, -LOG2E));
                        s2 = fmaf(p, lg, s2);
                        s3 = fmaf(p, __logf(fmaxf(p, 1e-12f)), s3);
                    }
                }
            }
            s1 += __shfl_xor_sync(0xffffffffu, s1, 1);
            s1 += __shfl_xor_sync(0xffffffffu, s1, 2);
            s2 += __shfl_xor_sync(0xffffffffu, s2, 1);
            s2 += __shfl_xor_sync(0xffffffffu, s2, 2);
            s3 += __shfl_xor_sync(0xffffffffu, s3, 1);
            s3 += __shfl_xor_sync(0xffffffffu, s3, 2);
            if ((lane & 3) == 0) {
                atomicAdd(&g_S1[r], s1);
                atomicAdd(&g_S2[r], s2);
                atomicAdd(&g_S3[r], s3);
            }
        }
    }
#endif
}

// ---------------- finalize: combine per-row stats + radial loss ----------------
__global__ __launch_bounds__(1024) void finalize_kernel(const float* __restrict__ TE,
                                                        float* __restrict__ out) {
    const int t = threadIdx.x;
    float v0 = 0.f, v1 = 0.f, v2 = 0.f, v3 = 0.f, v4 = 0.f;
    for (int r = t; r < MROWS; r += 1024) {
        v0 += g_S3[r] - g_S2[r] + 1.f + __logf(g_S1[r]);   // per-row KL
        float rr = g_rs[r];
        v1 += rr;
        float Hn = fminf(fmaxf(TE[r] * (1.f / LOG_V), 0.f), 1.f);
        float rtg = 3.0f / (1.f + expf(Hn));               // sigmoid(-H) * R_MAX
        float d = rr - rtg;
        v2 = fmaf(d, d, v2);
        v3 += rtg;
        v4 += Hn;
    }
    #pragma unroll
    for (int o = 16; o > 0; o >>= 1) {
        v0 += __shfl_xor_sync(0xffffffffu, v0, o);
        v1 += __shfl_xor_sync(0xffffffffu, v1, o);
        v2 += __shfl_xor_sync(0xffffffffu, v2, o);
        v3 += __shfl_xor_sync(0xffffffffu, v3, o);
        v4 += __shfl_xor_sync(0xffffffffu, v4, o);
    }
    __shared__ float sb[32][5];
    if ((t & 31) == 0) {
        int w = t >> 5;
        sb[w][0] = v0; sb[w][1] = v1; sb[w][2] = v2; sb[w][3] = v3; sb[w][4] = v4;
    }
    __syncthreads();
    if (t < 32) {
        float u0 = sb[t][0], u1 = sb[t][1], u2 = sb[t][2], u3 = sb[t][3], u4 = sb[t][4];
        #pragma unroll
        for (int o = 16; o > 0; o >>= 1) {
            u0 += __shfl_xor_sync(0xffffffffu, u0, o);
            u1 += __shfl_xor_sync(0xffffffffu, u1, o);
            u2 += __shfl_xor_sync(0xffffffffu, u2, o);
            u3 += __shfl_xor_sync(0xffffffffu, u3, o);
            u4 += __shfl_xor_sync(0xffffffffu, u4, o);
        }
        if (t == 0) {
            const float inv = 1.f / (float)MROWS;
            float l_ang = u0 * inv;
            float l_rad = u2 * inv;
            out[0] = l_ang + 0.1f * l_rad;
            out[1] = l_ang;
            out[2] = l_rad;
            out[3] = u1 * inv;   // mean r_s
            out[4] = u3 * inv;   // mean r_target
            out[5] = u4 * inv;   // mean H_norm
        }
    }
}

// ---------------- launch ----------------
extern "C" void kernel_launch(void* const* d_in, const int* in_sizes, int n_in,
                              void* d_out, int out_size) {
    const float* h  = (const float*)d_in[0];   // (2,1024,769)
    const float* W  = (const float*)d_in[1];   // (50257,769)
    const float* P  = (const float*)d_in[2];   // (2,1024,50257)
    const float* TE = (const float*)d_in[3];   // (2,1024)
    float* out = (float*)d_out;

    cudaFuncSetAttribute(gemm_fused_kernel,
                         cudaFuncAttributeMaxDynamicSharedMemorySize, DYN_SMEM);

    prep_w_kernel<<<NP / 8, 256>>>(W);
    prep_s_kernel<<<MROWS / 8, 256>>>(h);
    gemm_fused_kernel<<<dim3(MROWS / 128, NP / 128), 256, DYN_SMEM>>>(P);
    finalize_kernel<<<1, 1024>>>(TE, out);
}